// round 9
// baseline (speedup 1.0000x reference)
#include <cuda_runtime.h>
#include <cuda_fp16.h>
#include <cstdint>

// ---------------- problem dims ----------------
#define B_   128
#define T_   1024
#define TS_  1023
#define I_   256
#define H_   1024
#define O_   128
#define G3H  3072
#define BH_  (B_*H_)
#define NCTA 128         // persistent step CTAs (1/SM, co-resident)

// ---------------- device scratch (static; allocation-free rule) ----------------
__device__ __align__(16) __half g_seq_hi[(size_t)B_ * T_ * I_];
__device__ __align__(16) __half g_seq_lo[(size_t)B_ * T_ * I_];
__device__ __align__(16) __half g_wih_hi[(size_t)G3H * I_];
__device__ __align__(16) __half g_wih_lo[(size_t)G3H * I_];
__device__ __align__(16) __half g_whh_hi[(size_t)G3H * H_];
__device__ __align__(16) __half g_whh_lo[(size_t)G3H * H_];
__device__ __align__(16) __half g_wout[(size_t)O_ * H_];
__device__ __align__(16) __half g_h_hi[(size_t)TS_ * BH_];
__device__ __align__(16) __half g_h_lo[(size_t)TS_ * BH_];
__device__ __align__(16) __half g_hzero[BH_];
__device__ __align__(16) float g_gi[(size_t)B_ * T_ * G3H];
__device__ unsigned g_bar;

// ---------------- base-ISA helpers ----------------
__device__ __forceinline__ uint32_t s2u(const void* p) {
    return (uint32_t)__cvta_generic_to_shared(p);
}
__device__ __forceinline__ void cp16(uint32_t dst, const void* src) {
    asm volatile("cp.async.cg.shared.global [%0], [%1], 16;" :: "r"(dst), "l"(src));
}
__device__ __forceinline__ void cp_commit() { asm volatile("cp.async.commit_group;"); }
template <int N>
__device__ __forceinline__ void cp_wait() {
    asm volatile("cp.async.wait_group %0;" :: "n"(N));
}
__device__ __forceinline__ void ldsm_x4(unsigned& r0, unsigned& r1, unsigned& r2,
                                        unsigned& r3, uint32_t a) {
    asm volatile("ldmatrix.sync.aligned.m8n8.x4.shared.b16 {%0,%1,%2,%3}, [%4];"
                 : "=r"(r0), "=r"(r1), "=r"(r2), "=r"(r3) : "r"(a));
}
__device__ __forceinline__ void ldsm_x2(unsigned& r0, unsigned& r1, uint32_t a) {
    asm volatile("ldmatrix.sync.aligned.m8n8.x2.shared.b16 {%0,%1}, [%2];"
                 : "=r"(r0), "=r"(r1) : "r"(a));
}
__device__ __forceinline__ void mma16816(float* d, const unsigned* a, const unsigned* b) {
    asm volatile(
        "mma.sync.aligned.m16n8k16.row.col.f32.f16.f16.f32 "
        "{%0,%1,%2,%3}, {%4,%5,%6,%7}, {%8,%9}, {%0,%1,%2,%3};"
        : "+f"(d[0]), "+f"(d[1]), "+f"(d[2]), "+f"(d[3])
        : "r"(a[0]), "r"(a[1]), "r"(a[2]), "r"(a[3]), "r"(b[0]), "r"(b[1]));
}
__device__ __forceinline__ unsigned ldcg_u32(const unsigned* p) {
    unsigned v;
    asm volatile("ld.global.cg.u32 %0, [%1];" : "=r"(v) : "l"(p));
    return v;
}
__device__ __forceinline__ float sigm(float x) { return 1.0f / (1.0f + __expf(-x)); }
__device__ __forceinline__ float tanhfast(float x) {
    return 2.0f / (1.0f + __expf(-2.0f * x)) - 1.0f;
}

// ---------------- prep kernels ----------------
__global__ void k_conv_seq(const float* __restrict__ s) {
    size_t i = (size_t)blockIdx.x * blockDim.x + threadIdx.x;
    size_t n2 = (size_t)B_ * T_ * I_ / 2;
    if (i < n2) {
        float2 v = reinterpret_cast<const float2*>(s)[i];
        __half hx = __float2half_rn(v.x), hy = __float2half_rn(v.y);
        reinterpret_cast<__half2*>(g_seq_hi)[i] = __halves2half2(hx, hy);
        reinterpret_cast<__half2*>(g_seq_lo)[i] =
            __floats2half2_rn(v.x - __half2float(hx), v.y - __half2float(hy));
    }
}
__global__ void k_conv_w(const float* __restrict__ wih, const float* __restrict__ whh,
                         const float* __restrict__ wout) {
    const int nIH = G3H * I_;
    const int nHH = G3H * H_;
    const int nWO = O_ * H_;
    int i = blockIdx.x * blockDim.x + threadIdx.x;
    if (i == 0) g_bar = 0u;
    if (i < nIH) {
        float v = wih[i];
        __half h = __float2half_rn(v);
        g_wih_hi[i] = h;
        g_wih_lo[i] = __float2half_rn(v - __half2float(h));
    }
    int j = i - nIH;
    if (j >= 0 && j < nHH) {
        float v = whh[j];
        __half h = __float2half_rn(v);
        g_whh_hi[j] = h;
        g_whh_lo[j] = __float2half_rn(v - __half2float(h));
    }
    int k = i - nIH - nHH;
    if (k >= 0 && k < nWO) g_wout[k] = __float2half_rn(wout[k]);
    int z = i - nIH - nHH - nWO;
    if (z >= 0 && z < BH_ / 2) reinterpret_cast<uint32_t*>(g_hzero)[z] = 0u;
}

// Load a [128 x 64] fp16 tile (one plane) into swizzled SMEM.
__device__ __forceinline__ void load_p128(uint32_t dst, const __half* src, int stride) {
    for (int i = threadIdx.x; i < 1024; i += 256) {
        int r = i >> 3, cc = i & 7;
        cp16(dst + r * 128 + ((cc ^ (r & 7)) << 4),
             src + (size_t)r * stride + cc * 8);
    }
}
// Load a [64 x 64] tile, BOTH planes (hi at dst, lo at dst+8192).
__device__ __forceinline__ void load_a64(uint32_t dst, const __half* hi,
                                         const __half* lo, int stride) {
    for (int i = threadIdx.x; i < 1024; i += 256) {
        int p = i >> 9;
        int r = (i >> 3) & 63;
        int cc = i & 7;
        const __half* s = p ? lo : hi;
        cp16(dst + p * 8192 + r * 128 + ((cc ^ (r & 7)) << 4),
             s + (size_t)r * stride + cc * 8);
    }
}

// ---------------- gi = x @ W_ih^T (fp16-split, all timesteps) ----------------
// SMEM: A planes buf0 hi@0 lo@16384, buf1 hi@32768 lo@49152; B same +65536.
#define GI_SMEM 131072
__global__ void __launch_bounds__(256, 1)
k_gi(int dummy) {
    extern __shared__ char smem[];
    const uint32_t sb = s2u(smem);
    const int tid = threadIdx.x;
    const int lane = tid & 31, w = tid >> 5;
    const int M0 = blockIdx.x * 128, N0 = blockIdx.y * 128;
    const int m0 = (w & 3) * 32, n0 = (w >> 2) * 64;

    float acc[2][8][4];
#pragma unroll
    for (int a = 0; a < 2; a++)
#pragma unroll
        for (int b = 0; b < 8; b++)
#pragma unroll
            for (int c = 0; c < 4; c++) acc[a][b][c] = 0.0f;

    const int rA = m0 + (lane & 15);
    const int hiA = (lane >> 4) & 1;
    const int rBb = (lane & 7) + ((lane & 16) ? 8 : 0);
    const int hiB = (lane >> 3) & 1;

    const __half* aHi = g_seq_hi + (size_t)M0 * I_;
    const __half* aLo = g_seq_lo + (size_t)M0 * I_;
    const __half* bHi = g_wih_hi + (size_t)N0 * I_;
    const __half* bLo = g_wih_lo + (size_t)N0 * I_;

    load_p128(sb + 0,     aHi, I_);
    load_p128(sb + 16384, aLo, I_);
    load_p128(sb + 65536, bHi, I_);
    load_p128(sb + 81920, bLo, I_);
    cp_commit();
#pragma unroll 1
    for (int c = 0; c < 4; c++) {
        if (c < 3) {
            uint32_t ao = (c & 1) ? 0 : 32768;
            load_p128(sb + ao,          aHi + (c + 1) * 64, I_);
            load_p128(sb + ao + 16384,  aLo + (c + 1) * 64, I_);
            load_p128(sb + ao + 65536,  bHi + (c + 1) * 64, I_);
            load_p128(sb + ao + 81920,  bLo + (c + 1) * 64, I_);
            cp_commit();
            cp_wait<1>();
        } else {
            cp_wait<0>();
        }
        __syncthreads();
        const uint32_t ab = sb + ((c & 1) ? 32768 : 0);
        const uint32_t bb = ab + 65536;
#pragma unroll
        for (int kk = 0; kk < 4; kk++) {
            unsigned ah[2][4], al[2][4];
#pragma unroll
            for (int mi = 0; mi < 2; mi++) {
                int row = rA + mi * 16;
                uint32_t off = row * 128 + (((kk * 2 + hiA) ^ (row & 7)) << 4);
                ldsm_x4(ah[mi][0], ah[mi][1], ah[mi][2], ah[mi][3], ab + off);
                ldsm_x4(al[mi][0], al[mi][1], al[mi][2], al[mi][3], ab + 16384 + off);
            }
            unsigned bh[8][2], bl[8][2];
#pragma unroll
            for (int nt2 = 0; nt2 < 4; nt2++) {
                int row = n0 + nt2 * 16 + rBb;
                uint32_t off = row * 128 + (((kk * 2 + hiB) ^ (row & 7)) << 4);
                unsigned r0, r1, r2, r3;
                ldsm_x4(r0, r1, r2, r3, bb + off);
                bh[nt2 * 2][0] = r0; bh[nt2 * 2][1] = r1;
                bh[nt2 * 2 + 1][0] = r2; bh[nt2 * 2 + 1][1] = r3;
                ldsm_x4(r0, r1, r2, r3, bb + 16384 + off);
                bl[nt2 * 2][0] = r0; bl[nt2 * 2][1] = r1;
                bl[nt2 * 2 + 1][0] = r2; bl[nt2 * 2 + 1][1] = r3;
            }
#pragma unroll
            for (int mi = 0; mi < 2; mi++)
#pragma unroll
                for (int nt = 0; nt < 8; nt++) {
                    mma16816(acc[mi][nt], ah[mi], bh[nt]);
                    mma16816(acc[mi][nt], ah[mi], bl[nt]);
                    mma16816(acc[mi][nt], al[mi], bh[nt]);
                }
        }
        __syncthreads();
    }
#pragma unroll
    for (int mi = 0; mi < 2; mi++)
#pragma unroll
        for (int nt = 0; nt < 8; nt++) {
            int m = M0 + m0 + mi * 16 + (lane >> 2);
            int n = N0 + n0 + nt * 8 + 2 * (lane & 3);
            *reinterpret_cast<float2*>(g_gi + (size_t)m * G3H + n) =
                make_float2(acc[mi][nt][0], acc[mi][nt][1]);
            *reinterpret_cast<float2*>(g_gi + (size_t)(m + 8) * G3H + n) =
                make_float2(acc[mi][nt][2], acc[mi][nt][3]);
        }
}

// ---------------- persistent GRU recurrence (fp16-split) ----------------
// 128 CTAs: blk>>1 -> hidden [hid*16, +16) = 48 gate rows; blk&1 -> batch half (64).
// SMEM: W_hi 48x2048 @0, W_lo @98304, A dbuf @196608 (buf: hi 8KB + lo 8KB),
// gates fp32[48][68] overlay @196608. Total 229376.
#define SW_WLO 98304
#define SW_A   196608
#define SMEM_STEP 229376

__global__ void __launch_bounds__(256, 1)
k_step(const float* __restrict__ bih, const float* __restrict__ bhh) {
    extern __shared__ char smem[];
    const uint32_t sb = s2u(smem);
    float* gates = reinterpret_cast<float*>(smem + SW_A);
    const int tid = threadIdx.x;
    const int lane = tid & 31, w = tid >> 5;
    const int hid = blockIdx.x >> 1;
    const int half = blockIdx.x & 1;
    const int m0 = (w & 3) * 16;       // 4 m16 tiles over 64 batch rows
    const int n0 = (w >> 2) * 24;      // 2 warps x 24 gate rows

    // resident W slice (both planes): local row n -> global (n>>4)*H + hid*16 + (n&15)
    for (int i = tid; i < 12288; i += 256) {
        int p = i / 6144;
        int r2 = i - p * 6144;
        int n = r2 >> 7, cc = r2 & 127;
        int gr = (n >> 4) * H_ + hid * 16 + (n & 15);
        const __half* src = p ? g_whh_lo : g_whh_hi;
        cp16(sb + p * SW_WLO + n * 2048 + ((cc ^ (n & 7)) << 4),
             src + (size_t)gr * H_ + cc * 8);
    }
    cp_commit();
    cp_wait<0>();
    __syncthreads();

    // epilogue ownership: thread -> (b_local = tid>>2, 4 hidden units j4)
    const int b_local = tid >> 2;
    const int j4 = (tid & 3) * 4;
    const int b = half * 64 + b_local;
    const int jg0 = hid * 16 + j4;
    float br[4], bz[4], bni[4], bnh[4], hreg[4];
#pragma unroll
    for (int j = 0; j < 4; j++) {
        int jg = jg0 + j;
        br[j]  = bih[jg] + bhh[jg];
        bz[j]  = bih[H_ + jg] + bhh[H_ + jg];
        bni[j] = bih[2 * H_ + jg];
        bnh[j] = bhh[2 * H_ + jg];
        hreg[j] = 0.0f;
    }

    const int rA = m0 + (lane & 15);
    const int hiA = (lane >> 4) & 1;
    const int rB16 = (lane & 7) + ((lane & 16) ? 8 : 0);
    const int rB8 = lane & 7;
    const int hiB = (lane >> 3) & 1;

#pragma unroll 1
    for (int t = 0; t < TS_; t++) {
        const __half* hsHi;
        const __half* hsLo;
        if (t == 0) { hsHi = g_hzero; hsLo = g_hzero; }
        else {
            hsHi = g_h_hi + (size_t)(t - 1) * BH_;
            hsLo = g_h_lo + (size_t)(t - 1) * BH_;
        }
        hsHi += (size_t)(half * 64) * H_;
        hsLo += (size_t)(half * 64) * H_;

        float acc[3][4];
#pragma unroll
        for (int a = 0; a < 3; a++)
#pragma unroll
            for (int c = 0; c < 4; c++) acc[a][c] = 0.0f;

        load_a64(sb + SW_A, hsHi, hsLo, H_);
        cp_commit();
#pragma unroll 1
        for (int c = 0; c < 16; c++) {
            if (c < 15) {
                load_a64(sb + SW_A + (((c + 1) & 1) ? 16384 : 0),
                         hsHi + (c + 1) * 64, hsLo + (c + 1) * 64, H_);
                cp_commit();
                cp_wait<1>();
            } else {
                cp_wait<0>();
            }
            __syncthreads();
            const uint32_t ab = sb + SW_A + ((c & 1) ? 16384 : 0);
#pragma unroll
            for (int kk = 0; kk < 4; kk++) {
                unsigned ah[4], al[4];
                {
                    uint32_t off = rA * 128 + (((kk * 2 + hiA) ^ (rA & 7)) << 4);
                    ldsm_x4(ah[0], ah[1], ah[2], ah[3], ab + off);
                    ldsm_x4(al[0], al[1], al[2], al[3], ab + 8192 + off);
                }
                unsigned bh[3][2], bl[3][2];
                {
                    int cc = c * 8 + kk * 2 + hiB;
                    int nr = n0 + rB16;
                    uint32_t off16 = nr * 2048 + ((cc ^ (nr & 7)) << 4);
                    unsigned r0, r1, r2, r3;
                    ldsm_x4(r0, r1, r2, r3, sb + off16);
                    bh[0][0] = r0; bh[0][1] = r1; bh[1][0] = r2; bh[1][1] = r3;
                    ldsm_x4(r0, r1, r2, r3, sb + SW_WLO + off16);
                    bl[0][0] = r0; bl[0][1] = r1; bl[1][0] = r2; bl[1][1] = r3;
                    int nr8 = n0 + 16 + rB8;
                    uint32_t off8 = nr8 * 2048 + ((cc ^ (nr8 & 7)) << 4);
                    ldsm_x2(bh[2][0], bh[2][1], sb + off8);
                    ldsm_x2(bl[2][0], bl[2][1], sb + SW_WLO + off8);
                }
#pragma unroll
                for (int nt = 0; nt < 3; nt++) {
                    mma16816(acc[nt], ah, bh[nt]);
                    mma16816(acc[nt], ah, bl[nt]);
                    mma16816(acc[nt], al, bh[nt]);
                }
            }
            __syncthreads();
        }

        // stash gates into overlay [n][68]
#pragma unroll
        for (int nt = 0; nt < 3; nt++) {
            int m = m0 + (lane >> 2);
            int n = n0 + nt * 8 + 2 * (lane & 3);
            gates[n * 68 + m]           = acc[nt][0];
            gates[(n + 1) * 68 + m]     = acc[nt][1];
            gates[n * 68 + m + 8]       = acc[nt][2];
            gates[(n + 1) * 68 + m + 8] = acc[nt][3];
        }
        __syncthreads();

        // fused GRU update
        {
            const float* gi = g_gi + ((size_t)b * T_ + t) * G3H;
            float4 gr = *reinterpret_cast<const float4*>(gi + jg0);
            float4 gz = *reinterpret_cast<const float4*>(gi + H_ + jg0);
            float4 gn = *reinterpret_cast<const float4*>(gi + 2 * H_ + jg0);
            float gir[4] = {gr.x, gr.y, gr.z, gr.w};
            float giz[4] = {gz.x, gz.y, gz.z, gz.w};
            float gin[4] = {gn.x, gn.y, gn.z, gn.w};
            __half hi4[4], lo4[4];
#pragma unroll
            for (int j = 0; j < 4; j++) {
                int jl = j4 + j;
                float r = sigm(gir[j] + gates[jl * 68 + b_local] + br[j]);
                float z = sigm(giz[j] + gates[(16 + jl) * 68 + b_local] + bz[j]);
                float n = tanhfast(gin[j] + bni[j] +
                                   r * (gates[(32 + jl) * 68 + b_local] + bnh[j]));
                float h = n + z * (hreg[j] - n);
                hreg[j] = h;
                hi4[j] = __float2half_rn(h);
                lo4[j] = __float2half_rn(h - __half2float(hi4[j]));
            }
            size_t off = (size_t)t * BH_ + (size_t)b * H_ + jg0;
            *reinterpret_cast<uint2*>(g_h_hi + off) = *reinterpret_cast<uint2*>(hi4);
            *reinterpret_cast<uint2*>(g_h_lo + off) = *reinterpret_cast<uint2*>(lo4);
        }

        // grid barrier
        if (t < TS_ - 1) {
            __threadfence();
            __syncthreads();
            if (tid == 0) {
                atomicAdd(&g_bar, 1u);
                unsigned target = (unsigned)NCTA * (unsigned)(t + 1);
                while (ldcg_u32(&g_bar) < target) { __nanosleep(64); }
            }
            __syncthreads();
        }
    }
}

// ---------------- output GEMM + log_softmax (one CTA per timestep) ----------------
#define SMEM_OUT (128*129*4)
__global__ void __launch_bounds__(256, 1)
k_out(const float* __restrict__ bout, float* __restrict__ out) {
    extern __shared__ char smem[];
    const uint32_t sb = s2u(smem);
    const uint32_t A0 = sb, A1 = sb + 16384, Bb0 = sb + 32768, Bb1 = sb + 49152;
    float* sC = reinterpret_cast<float*>(smem);
    const int tid = threadIdx.x;
    const int lane = tid & 31, w = tid >> 5;
    const int t = blockIdx.x;
    const int m0 = (w & 3) * 32, n0 = (w >> 2) * 64;

    float acc[2][8][4];
#pragma unroll
    for (int a = 0; a < 2; a++)
#pragma unroll
        for (int b = 0; b < 8; b++)
#pragma unroll
            for (int c = 0; c < 4; c++) acc[a][b][c] = 0.0f;

    const int rA = m0 + (lane & 15);
    const int hiA = (lane >> 4) & 1;
    const int rBb = (lane & 7) + ((lane & 16) ? 8 : 0);
    const int hiB = (lane >> 3) & 1;
    const __half* hsrc = g_h_hi + (size_t)t * BH_;

    load_p128(A0, hsrc, H_);
    load_p128(Bb0, g_wout, H_);
    cp_commit();
#pragma unroll 1
    for (int c = 0; c < 16; c++) {
        if (c < 15) {
            load_p128(((c & 1) ? A0 : A1), hsrc + (c + 1) * 64, H_);
            load_p128(((c & 1) ? Bb0 : Bb1), g_wout + (c + 1) * 64, H_);
            cp_commit();
            cp_wait<1>();
        } else {
            cp_wait<0>();
        }
        __syncthreads();
        const uint32_t ab = (c & 1) ? A1 : A0;
        const uint32_t bb = (c & 1) ? Bb1 : Bb0;
#pragma unroll
        for (int kk = 0; kk < 4; kk++) {
            unsigned afr[2][4];
#pragma unroll
            for (int mi = 0; mi < 2; mi++) {
                int row = rA + mi * 16;
                ldsm_x4(afr[mi][0], afr[mi][1], afr[mi][2], afr[mi][3],
                        ab + row * 128 + (((kk * 2 + hiA) ^ (row & 7)) << 4));
            }
            unsigned bfr[8][2];
#pragma unroll
            for (int nt2 = 0; nt2 < 4; nt2++) {
                int row = n0 + nt2 * 16 + rBb;
                unsigned r0, r1, r2, r3;
                ldsm_x4(r0, r1, r2, r3,
                        bb + row * 128 + (((kk * 2 + hiB) ^ (row & 7)) << 4));
                bfr[nt2 * 2][0] = r0; bfr[nt2 * 2][1] = r1;
                bfr[nt2 * 2 + 1][0] = r2; bfr[nt2 * 2 + 1][1] = r3;
            }
#pragma unroll
            for (int mi = 0; mi < 2; mi++)
#pragma unroll
                for (int nt = 0; nt < 8; nt++)
                    mma16816(acc[mi][nt], afr[mi], bfr[nt]);
        }
        __syncthreads();
    }

#pragma unroll
    for (int mi = 0; mi < 2; mi++)
#pragma unroll
        for (int nt = 0; nt < 8; nt++) {
            int m = m0 + mi * 16 + (lane >> 2);
            int n = n0 + nt * 8 + 2 * (lane & 3);
            sC[m * 129 + n]           = acc[mi][nt][0];
            sC[m * 129 + n + 1]       = acc[mi][nt][1];
            sC[(m + 8) * 129 + n]     = acc[mi][nt][2];
            sC[(m + 8) * 129 + n + 1] = acc[mi][nt][3];
        }
    __syncthreads();

    if (tid < 128) {
        const int b = tid;
        float mx = -3.4e38f;
#pragma unroll 4
        for (int o = 0; o < 128; o++) {
            float x = sC[b * 129 + o] + bout[o];
            mx = fmaxf(mx, x);
        }
        float s = 0.0f;
#pragma unroll 4
        for (int o = 0; o < 128; o++)
            s += __expf(sC[b * 129 + o] + bout[o] - mx);
        const float lse = mx + __logf(s);
        float* dst = out + ((size_t)b * TS_ + t) * O_;
#pragma unroll 4
        for (int o = 0; o < 128; o += 4) {
            float4 v = make_float4(sC[b * 129 + o] + bout[o] - lse,
                                   sC[b * 129 + o + 1] + bout[o + 1] - lse,
                                   sC[b * 129 + o + 2] + bout[o + 2] - lse,
                                   sC[b * 129 + o + 3] + bout[o + 3] - lse);
            *reinterpret_cast<float4*>(dst + o) = v;
        }
    }
}

// ---------------- host ----------------
extern "C" void kernel_launch(void* const* d_in, const int* in_sizes, int n_in,
                              void* d_out, int out_size) {
    const float* seq  = (const float*)d_in[0];
    const float* wih  = (const float*)d_in[1];
    const float* whh  = (const float*)d_in[2];
    const float* bih  = (const float*)d_in[3];
    const float* bhh  = (const float*)d_in[4];
    const float* wout = (const float*)d_in[5];
    const float* bout = (const float*)d_in[6];
    float* out = (float*)d_out;

    static bool attr_done = false;
    if (!attr_done) {
        cudaFuncSetAttribute(k_gi,   cudaFuncAttributeMaxDynamicSharedMemorySize, GI_SMEM);
        cudaFuncSetAttribute(k_step, cudaFuncAttributeMaxDynamicSharedMemorySize, SMEM_STEP);
        cudaFuncSetAttribute(k_out,  cudaFuncAttributeMaxDynamicSharedMemorySize, SMEM_OUT);
        attr_done = true;
    }

    {
        size_t n2 = (size_t)B_ * T_ * I_ / 2;
        k_conv_seq<<<(unsigned)((n2 + 255) / 256), 256>>>(seq);
    }
    {
        int total = G3H * I_ + G3H * H_ + O_ * H_ + BH_ / 2;
        k_conv_w<<<(total + 255) / 256, 256>>>(wih, whh, wout);
    }
    {
        dim3 grid(1024, 24);
        k_gi<<<grid, 256, GI_SMEM>>>(0);
    }
    k_step<<<NCTA, 256, SMEM_STEP>>>(bih, bhh);
    k_out<<<TS_, 256, SMEM_OUT>>>(bout, out);
}

// round 12
// speedup vs baseline: 1.0878x; 1.0878x over previous
#include <cuda_runtime.h>
#include <cuda_fp16.h>
#include <cstdint>

// ---------------- problem dims ----------------
#define B_   128
#define T_   1024
#define TS_  1023
#define I_   256
#define H_   1024
#define O_   128
#define G3H  3072
#define BH_  (B_*H_)
#define NCTA 128         // persistent step CTAs (1/SM, co-resident)

// ---------------- device scratch (static; allocation-free rule) ----------------
__device__ __align__(16) __half g_seq_hi[(size_t)B_ * T_ * I_];
__device__ __align__(16) __half g_seq_lo[(size_t)B_ * T_ * I_];
__device__ __align__(16) __half g_wih_hi[(size_t)G3H * I_];
__device__ __align__(16) __half g_wih_lo[(size_t)G3H * I_];
__device__ __align__(16) __half g_whh_hi[(size_t)G3H * H_];
__device__ __align__(16) __half g_whh_lo[(size_t)G3H * H_];
__device__ __align__(16) __half g_wout[(size_t)O_ * H_];
__device__ __align__(16) __half g_h_hi[(size_t)TS_ * BH_];
__device__ __align__(16) __half g_h_lo[(size_t)TS_ * BH_];
__device__ __align__(16) __half g_hzero[BH_];
__device__ __align__(16) float g_gi[(size_t)B_ * T_ * G3H];
__device__ unsigned g_bar;

// ---------------- base-ISA helpers ----------------
__device__ __forceinline__ uint32_t s2u(const void* p) {
    return (uint32_t)__cvta_generic_to_shared(p);
}
__device__ __forceinline__ void cp16(uint32_t dst, const void* src) {
    asm volatile("cp.async.cg.shared.global [%0], [%1], 16;" :: "r"(dst), "l"(src));
}
__device__ __forceinline__ void cp_commit() { asm volatile("cp.async.commit_group;"); }
template <int N>
__device__ __forceinline__ void cp_wait() {
    asm volatile("cp.async.wait_group %0;" :: "n"(N));
}
__device__ __forceinline__ void ldsm_x4(unsigned& r0, unsigned& r1, unsigned& r2,
                                        unsigned& r3, uint32_t a) {
    asm volatile("ldmatrix.sync.aligned.m8n8.x4.shared.b16 {%0,%1,%2,%3}, [%4];"
                 : "=r"(r0), "=r"(r1), "=r"(r2), "=r"(r3) : "r"(a));
}
__device__ __forceinline__ void ldsm_x2(unsigned& r0, unsigned& r1, uint32_t a) {
    asm volatile("ldmatrix.sync.aligned.m8n8.x2.shared.b16 {%0,%1}, [%2];"
                 : "=r"(r0), "=r"(r1) : "r"(a));
}
__device__ __forceinline__ void mma16816(float* d, const unsigned* a, const unsigned* b) {
    asm volatile(
        "mma.sync.aligned.m16n8k16.row.col.f32.f16.f16.f32 "
        "{%0,%1,%2,%3}, {%4,%5,%6,%7}, {%8,%9}, {%0,%1,%2,%3};"
        : "+f"(d[0]), "+f"(d[1]), "+f"(d[2]), "+f"(d[3])
        : "r"(a[0]), "r"(a[1]), "r"(a[2]), "r"(a[3]), "r"(b[0]), "r"(b[1]));
}
__device__ __forceinline__ unsigned ldcg_u32(const unsigned* p) {
    unsigned v;
    asm volatile("ld.global.cg.u32 %0, [%1];" : "=r"(v) : "l"(p));
    return v;
}
__device__ __forceinline__ float sigm(float x) { return 1.0f / (1.0f + __expf(-x)); }
__device__ __forceinline__ float tanhfast(float x) {
    return 2.0f / (1.0f + __expf(-2.0f * x)) - 1.0f;
}

// ---------------- prep kernels ----------------
__global__ void k_conv_seq(const float* __restrict__ s) {
    size_t i = (size_t)blockIdx.x * blockDim.x + threadIdx.x;
    size_t n2 = (size_t)B_ * T_ * I_ / 2;
    if (i < n2) {
        float2 v = reinterpret_cast<const float2*>(s)[i];
        __half hx = __float2half_rn(v.x), hy = __float2half_rn(v.y);
        reinterpret_cast<__half2*>(g_seq_hi)[i] = __halves2half2(hx, hy);
        reinterpret_cast<__half2*>(g_seq_lo)[i] =
            __floats2half2_rn(v.x - __half2float(hx), v.y - __half2float(hy));
    }
}
__global__ void k_conv_w(const float* __restrict__ wih, const float* __restrict__ whh,
                         const float* __restrict__ wout) {
    const int nIH = G3H * I_;
    const int nHH = G3H * H_;
    const int nWO = O_ * H_;
    int i = blockIdx.x * blockDim.x + threadIdx.x;
    if (i == 0) g_bar = 0u;
    if (i < nIH) {
        float v = wih[i];
        __half h = __float2half_rn(v);
        g_wih_hi[i] = h;
        g_wih_lo[i] = __float2half_rn(v - __half2float(h));
    }
    int j = i - nIH;
    if (j >= 0 && j < nHH) {
        float v = whh[j];
        __half h = __float2half_rn(v);
        g_whh_hi[j] = h;
        g_whh_lo[j] = __float2half_rn(v - __half2float(h));
    }
    int k = i - nIH - nHH;
    if (k >= 0 && k < nWO) g_wout[k] = __float2half_rn(wout[k]);
    int z = i - nIH - nHH - nWO;
    if (z >= 0 && z < BH_ / 2) reinterpret_cast<uint32_t*>(g_hzero)[z] = 0u;
}

// Load a [128 x 64] fp16 tile (one plane) into swizzled SMEM.
__device__ __forceinline__ void load_p128(uint32_t dst, const __half* src, int stride) {
    for (int i = threadIdx.x; i < 1024; i += 256) {
        int r = i >> 3, cc = i & 7;
        cp16(dst + r * 128 + ((cc ^ (r & 7)) << 4),
             src + (size_t)r * stride + cc * 8);
    }
}
// Load a [64 x 64] tile, BOTH planes (hi at dst, lo at dst+8192).
__device__ __forceinline__ void load_a64(uint32_t dst, const __half* hi,
                                         const __half* lo, int stride) {
    for (int i = threadIdx.x; i < 1024; i += 256) {
        int p = i >> 9;
        int r = (i >> 3) & 63;
        int cc = i & 7;
        const __half* s = p ? lo : hi;
        cp16(dst + p * 8192 + r * 128 + ((cc ^ (r & 7)) << 4),
             s + (size_t)r * stride + cc * 8);
    }
}

// ---------------- gi = x @ W_ih^T (fp16-split, all timesteps) ----------------
#define GI_SMEM 131072
__global__ void __launch_bounds__(256, 1)
k_gi(int dummy) {
    extern __shared__ char smem[];
    const uint32_t sb = s2u(smem);
    const int tid = threadIdx.x;
    const int lane = tid & 31, w = tid >> 5;
    const int M0 = blockIdx.x * 128, N0 = blockIdx.y * 128;
    const int m0 = (w & 3) * 32, n0 = (w >> 2) * 64;

    float acc[2][8][4];
#pragma unroll
    for (int a = 0; a < 2; a++)
#pragma unroll
        for (int b = 0; b < 8; b++)
#pragma unroll
            for (int c = 0; c < 4; c++) acc[a][b][c] = 0.0f;

    const int rA = m0 + (lane & 15);
    const int hiA = (lane >> 4) & 1;
    const int rBb = (lane & 7) + ((lane & 16) ? 8 : 0);
    const int hiB = (lane >> 3) & 1;

    const __half* aHi = g_seq_hi + (size_t)M0 * I_;
    const __half* aLo = g_seq_lo + (size_t)M0 * I_;
    const __half* bHi = g_wih_hi + (size_t)N0 * I_;
    const __half* bLo = g_wih_lo + (size_t)N0 * I_;

    load_p128(sb + 0,     aHi, I_);
    load_p128(sb + 16384, aLo, I_);
    load_p128(sb + 65536, bHi, I_);
    load_p128(sb + 81920, bLo, I_);
    cp_commit();
#pragma unroll 1
    for (int c = 0; c < 4; c++) {
        if (c < 3) {
            uint32_t ao = (c & 1) ? 0 : 32768;
            load_p128(sb + ao,          aHi + (c + 1) * 64, I_);
            load_p128(sb + ao + 16384,  aLo + (c + 1) * 64, I_);
            load_p128(sb + ao + 65536,  bHi + (c + 1) * 64, I_);
            load_p128(sb + ao + 81920,  bLo + (c + 1) * 64, I_);
            cp_commit();
            cp_wait<1>();
        } else {
            cp_wait<0>();
        }
        __syncthreads();
        const uint32_t ab = sb + ((c & 1) ? 32768 : 0);
        const uint32_t bb = ab + 65536;
#pragma unroll
        for (int kk = 0; kk < 4; kk++) {
            unsigned ah[2][4], al[2][4];
#pragma unroll
            for (int mi = 0; mi < 2; mi++) {
                int row = rA + mi * 16;
                uint32_t off = row * 128 + (((kk * 2 + hiA) ^ (row & 7)) << 4);
                ldsm_x4(ah[mi][0], ah[mi][1], ah[mi][2], ah[mi][3], ab + off);
                ldsm_x4(al[mi][0], al[mi][1], al[mi][2], al[mi][3], ab + 16384 + off);
            }
            unsigned bh[8][2], bl[8][2];
#pragma unroll
            for (int nt2 = 0; nt2 < 4; nt2++) {
                int row = n0 + nt2 * 16 + rBb;
                uint32_t off = row * 128 + (((kk * 2 + hiB) ^ (row & 7)) << 4);
                unsigned r0, r1, r2, r3;
                ldsm_x4(r0, r1, r2, r3, bb + off);
                bh[nt2 * 2][0] = r0; bh[nt2 * 2][1] = r1;
                bh[nt2 * 2 + 1][0] = r2; bh[nt2 * 2 + 1][1] = r3;
                ldsm_x4(r0, r1, r2, r3, bb + 16384 + off);
                bl[nt2 * 2][0] = r0; bl[nt2 * 2][1] = r1;
                bl[nt2 * 2 + 1][0] = r2; bl[nt2 * 2 + 1][1] = r3;
            }
#pragma unroll
            for (int mi = 0; mi < 2; mi++)
#pragma unroll
                for (int nt = 0; nt < 8; nt++) {
                    mma16816(acc[mi][nt], ah[mi], bh[nt]);
                    mma16816(acc[mi][nt], ah[mi], bl[nt]);
                    mma16816(acc[mi][nt], al[mi], bh[nt]);
                }
        }
        __syncthreads();
    }
#pragma unroll
    for (int mi = 0; mi < 2; mi++)
#pragma unroll
        for (int nt = 0; nt < 8; nt++) {
            int m = M0 + m0 + mi * 16 + (lane >> 2);
            int n = N0 + n0 + nt * 8 + 2 * (lane & 3);
            *reinterpret_cast<float2*>(g_gi + (size_t)m * G3H + n) =
                make_float2(acc[mi][nt][0], acc[mi][nt][1]);
            *reinterpret_cast<float2*>(g_gi + (size_t)(m + 8) * G3H + n) =
                make_float2(acc[mi][nt][2], acc[mi][nt][3]);
        }
}

// ---------------- persistent GRU recurrence (fp16-split, kk-split warps) ----------------
// 128 CTAs: blk>>1 -> hidden [hid*16,+16) = 48 gate rows; blk&1 -> batch half (64).
// 8 warps = 2 k-halves (ks) x 2 m-groups (mg: 32 rows) x 2 n-groups (ng: 24 rows).
// SMEM: W_hi 48x2048 @0, W_lo @98304, A dbuf @196608 (2 x (hi 8KB + lo 8KB)),
// gates fp32 2x[48][69] overlay A region. Total 229376.
#define SW_WLO 98304
#define SW_A   196608
#define GATES_SZ 13248       // 48*69*4
#define SMEM_STEP 229376

__global__ void __launch_bounds__(256, 1)
k_step(const float* __restrict__ bih, const float* __restrict__ bhh) {
    extern __shared__ char smem[];
    const uint32_t sb = s2u(smem);
    float* gates0 = reinterpret_cast<float*>(smem + SW_A);
    float* gates1 = reinterpret_cast<float*>(smem + SW_A + GATES_SZ);
    const int tid = threadIdx.x;
    const int lane = tid & 31, w = tid >> 5;
    const int hid = blockIdx.x >> 1;
    const int half = blockIdx.x & 1;
    const int ks = w >> 2;          // kk-split half: kk in {2ks, 2ks+1}
    const int mg = w & 1;           // m-group: rows mg*32..+32 (2 m16 tiles)
    const int ng = (w >> 1) & 1;    // n-group: rows ng*24..+24
    const int n0 = ng * 24;
    float* gatesW = ks ? gates1 : gates0;

    // resident W slice (both planes): local row n -> global (n>>4)*H + hid*16 + (n&15)
    for (int i = tid; i < 12288; i += 256) {
        int p = i / 6144;
        int r2 = i - p * 6144;
        int n = r2 >> 7, cc = r2 & 127;
        int gr = (n >> 4) * H_ + hid * 16 + (n & 15);
        const __half* src = p ? g_whh_lo : g_whh_hi;
        cp16(sb + p * SW_WLO + n * 2048 + ((cc ^ (n & 7)) << 4),
             src + (size_t)gr * H_ + cc * 8);
    }
    cp_commit();
    cp_wait<0>();
    __syncthreads();

    // epilogue ownership: thread -> (b_local = tid>>2, 4 hidden units j4)
    const int b_local = tid >> 2;
    const int j4 = (tid & 3) * 4;
    const int b = half * 64 + b_local;
    const int jg0 = hid * 16 + j4;
    float br[4], bz[4], bni[4], bnh[4], hreg[4];
#pragma unroll
    for (int j = 0; j < 4; j++) {
        int jg = jg0 + j;
        br[j]  = bih[jg] + bhh[jg];
        bz[j]  = bih[H_ + jg] + bhh[H_ + jg];
        bni[j] = bih[2 * H_ + jg];
        bnh[j] = bhh[2 * H_ + jg];
        hreg[j] = 0.0f;
    }

    const int rA0 = mg * 32 + (lane & 15);
    const int hiA = (lane >> 4) & 1;
    const int rB16 = (lane & 7) + ((lane & 16) ? 8 : 0);
    const int rB8 = lane & 7;
    const int hiB = (lane >> 3) & 1;

#pragma unroll 1
    for (int t = 0; t < TS_; t++) {
        const __half* hsHi;
        const __half* hsLo;
        if (t == 0) { hsHi = g_hzero; hsLo = g_hzero; }
        else {
            hsHi = g_h_hi + (size_t)(t - 1) * BH_;
            hsLo = g_h_lo + (size_t)(t - 1) * BH_;
        }
        hsHi += (size_t)(half * 64) * H_;
        hsLo += (size_t)(half * 64) * H_;

        float acc[2][3][4];
#pragma unroll
        for (int a = 0; a < 2; a++)
#pragma unroll
            for (int bq = 0; bq < 3; bq++)
#pragma unroll
                for (int c = 0; c < 4; c++) acc[a][bq][c] = 0.0f;

        float4 pgr, pgz, pgn;   // gi prefetch (filled at c==13)
        pgr.x = pgr.y = pgr.z = pgr.w = 0.0f;
        pgz = pgr; pgn = pgr;

        load_a64(sb + SW_A, hsHi, hsLo, H_);
        cp_commit();
#pragma unroll 1
        for (int c = 0; c < 16; c++) {
            cp_wait<0>();        // chunk c landed
            __syncthreads();     // everyone done computing chunk c-1 (buffer reuse guard)
            if (c < 15) {
                load_a64(sb + SW_A + (((c + 1) & 1) ? 16384 : 0),
                         hsHi + (c + 1) * 64, hsLo + (c + 1) * 64, H_);
                cp_commit();
            }
            if (c == 13) {
                const float* gip = g_gi + ((size_t)b * T_ + t) * G3H;
                pgr = __ldcs(reinterpret_cast<const float4*>(gip + jg0));
                pgz = __ldcs(reinterpret_cast<const float4*>(gip + H_ + jg0));
                pgn = __ldcs(reinterpret_cast<const float4*>(gip + 2 * H_ + jg0));
            }
            const uint32_t ab = sb + SW_A + ((c & 1) ? 16384 : 0);
#pragma unroll
            for (int k2 = 0; k2 < 2; k2++) {
                const int kk = ks * 2 + k2;
                unsigned ah[2][4], al[2][4];
#pragma unroll
                for (int mi = 0; mi < 2; mi++) {
                    int row = rA0 + mi * 16;
                    uint32_t off = row * 128 + (((kk * 2 + hiA) ^ (row & 7)) << 4);
                    ldsm_x4(ah[mi][0], ah[mi][1], ah[mi][2], ah[mi][3], ab + off);
                    ldsm_x4(al[mi][0], al[mi][1], al[mi][2], al[mi][3], ab + 8192 + off);
                }
                unsigned bh[3][2], bl[3][2];
                {
                    int cc = c * 8 + kk * 2 + hiB;
                    int nr = n0 + rB16;
                    uint32_t off16 = nr * 2048 + ((cc ^ (nr & 7)) << 4);
                    unsigned r0, r1, r2, r3;
                    ldsm_x4(r0, r1, r2, r3, sb + off16);
                    bh[0][0] = r0; bh[0][1] = r1; bh[1][0] = r2; bh[1][1] = r3;
                    ldsm_x4(r0, r1, r2, r3, sb + SW_WLO + off16);
                    bl[0][0] = r0; bl[0][1] = r1; bl[1][0] = r2; bl[1][1] = r3;
                    int nr8 = n0 + 16 + rB8;
                    uint32_t off8 = nr8 * 2048 + ((cc ^ (nr8 & 7)) << 4);
                    ldsm_x2(bh[2][0], bh[2][1], sb + off8);
                    ldsm_x2(bl[2][0], bl[2][1], sb + SW_WLO + off8);
                }
#pragma unroll
                for (int mi = 0; mi < 2; mi++)
#pragma unroll
                    for (int nt = 0; nt < 3; nt++) {
                        mma16816(acc[mi][nt], ah[mi], bh[nt]);
                        mma16816(acc[mi][nt], ah[mi], bl[nt]);
                        mma16816(acc[mi][nt], al[mi], bh[nt]);
                    }
            }
        }
        __syncthreads();   // all compute done before gates overlay both A buffers

        // stash partial gates: wg0 -> gates0, wg1 -> gates1  (stride 69: conflict-free)
#pragma unroll
        for (int mi = 0; mi < 2; mi++)
#pragma unroll
            for (int nt = 0; nt < 3; nt++) {
                int m = mg * 32 + mi * 16 + (lane >> 2);
                int n = n0 + nt * 8 + 2 * (lane & 3);
                gatesW[n * 69 + m]           = acc[mi][nt][0];
                gatesW[(n + 1) * 69 + m]     = acc[mi][nt][1];
                gatesW[n * 69 + m + 8]       = acc[mi][nt][2];
                gatesW[(n + 1) * 69 + m + 8] = acc[mi][nt][3];
            }
        __syncthreads();

        // fused GRU update (thread owns (b, 4 hidden units)); sums the two k-partials
        {
            float gir[4] = {pgr.x, pgr.y, pgr.z, pgr.w};
            float giz[4] = {pgz.x, pgz.y, pgz.z, pgz.w};
            float gin[4] = {pgn.x, pgn.y, pgn.z, pgn.w};
            __half hi4[4], lo4[4];
#pragma unroll
            for (int j = 0; j < 4; j++) {
                int jl = j4 + j;
                float sr = gates0[jl * 69 + b_local]        + gates1[jl * 69 + b_local];
                float sz = gates0[(16 + jl) * 69 + b_local] + gates1[(16 + jl) * 69 + b_local];
                float sn = gates0[(32 + jl) * 69 + b_local] + gates1[(32 + jl) * 69 + b_local];
                float r = sigm(gir[j] + sr + br[j]);
                float z = sigm(giz[j] + sz + bz[j]);
                float n = tanhfast(gin[j] + bni[j] + r * (sn + bnh[j]));
                float h = n + z * (hreg[j] - n);
                hreg[j] = h;
                hi4[j] = __float2half_rn(h);
                lo4[j] = __float2half_rn(h - __half2float(hi4[j]));
            }
            size_t off = (size_t)t * BH_ + (size_t)b * H_ + jg0;
            *reinterpret_cast<uint2*>(g_h_hi + off) = *reinterpret_cast<uint2*>(hi4);
            *reinterpret_cast<uint2*>(g_h_lo + off) = *reinterpret_cast<uint2*>(lo4);
        }

        // grid barrier
        if (t < TS_ - 1) {
            __threadfence();
            __syncthreads();
            if (tid == 0) {
                atomicAdd(&g_bar, 1u);
                unsigned target = (unsigned)NCTA * (unsigned)(t + 1);
                while (ldcg_u32(&g_bar) < target) {}
            }
            __syncthreads();
        }
    }
}

// ---------------- output GEMM + log_softmax (one CTA per timestep) ----------------
#define SMEM_OUT (128*129*4)
__global__ void __launch_bounds__(256, 1)
k_out(const float* __restrict__ bout, float* __restrict__ out) {
    extern __shared__ char smem[];
    const uint32_t sb = s2u(smem);
    const uint32_t A0 = sb, A1 = sb + 16384, Bb0 = sb + 32768, Bb1 = sb + 49152;
    float* sC = reinterpret_cast<float*>(smem);
    const int tid = threadIdx.x;
    const int lane = tid & 31, w = tid >> 5;
    const int t = blockIdx.x;
    const int m0 = (w & 3) * 32, n0 = (w >> 2) * 64;

    float acc[2][8][4];
#pragma unroll
    for (int a = 0; a < 2; a++)
#pragma unroll
        for (int b = 0; b < 8; b++)
#pragma unroll
            for (int c = 0; c < 4; c++) acc[a][b][c] = 0.0f;

    const int rA = m0 + (lane & 15);
    const int hiA = (lane >> 4) & 1;
    const int rBb = (lane & 7) + ((lane & 16) ? 8 : 0);
    const int hiB = (lane >> 3) & 1;
    const __half* hsrc = g_h_hi + (size_t)t * BH_;

    load_p128(A0, hsrc, H_);
    load_p128(Bb0, g_wout, H_);
    cp_commit();
#pragma unroll 1
    for (int c = 0; c < 16; c++) {
        if (c < 15) {
            load_p128(((c & 1) ? A0 : A1), hsrc + (c + 1) * 64, H_);
            load_p128(((c & 1) ? Bb0 : Bb1), g_wout + (c + 1) * 64, H_);
            cp_commit();
            cp_wait<1>();
        } else {
            cp_wait<0>();
        }
        __syncthreads();
        const uint32_t ab = (c & 1) ? A1 : A0;
        const uint32_t bb = (c & 1) ? Bb1 : Bb0;
#pragma unroll
        for (int kk = 0; kk < 4; kk++) {
            unsigned afr[2][4];
#pragma unroll
            for (int mi = 0; mi < 2; mi++) {
                int row = rA + mi * 16;
                ldsm_x4(afr[mi][0], afr[mi][1], afr[mi][2], afr[mi][3],
                        ab + row * 128 + (((kk * 2 + hiA) ^ (row & 7)) << 4));
            }
            unsigned bfr[8][2];
#pragma unroll
            for (int nt2 = 0; nt2 < 4; nt2++) {
                int row = n0 + nt2 * 16 + rBb;
                unsigned r0, r1, r2, r3;
                ldsm_x4(r0, r1, r2, r3,
                        bb + row * 128 + (((kk * 2 + hiB) ^ (row & 7)) << 4));
                bfr[nt2 * 2][0] = r0; bfr[nt2 * 2][1] = r1;
                bfr[nt2 * 2 + 1][0] = r2; bfr[nt2 * 2 + 1][1] = r3;
            }
#pragma unroll
            for (int mi = 0; mi < 2; mi++)
#pragma unroll
                for (int nt = 0; nt < 8; nt++)
                    mma16816(acc[mi][nt], afr[mi], bfr[nt]);
        }
        __syncthreads();
    }

#pragma unroll
    for (int mi = 0; mi < 2; mi++)
#pragma unroll
        for (int nt = 0; nt < 8; nt++) {
            int m = m0 + mi * 16 + (lane >> 2);
            int n = n0 + nt * 8 + 2 * (lane & 3);
            sC[m * 129 + n]           = acc[mi][nt][0];
            sC[m * 129 + n + 1]       = acc[mi][nt][1];
            sC[(m + 8) * 129 + n]     = acc[mi][nt][2];
            sC[(m + 8) * 129 + n + 1] = acc[mi][nt][3];
        }
    __syncthreads();

    if (tid < 128) {
        const int b = tid;
        float mx = -3.4e38f;
#pragma unroll 4
        for (int o = 0; o < 128; o++) {
            float x = sC[b * 129 + o] + bout[o];
            mx = fmaxf(mx, x);
        }
        float s = 0.0f;
#pragma unroll 4
        for (int o = 0; o < 128; o++)
            s += __expf(sC[b * 129 + o] + bout[o] - mx);
        const float lse = mx + __logf(s);
        float* dst = out + ((size_t)b * TS_ + t) * O_;
#pragma unroll 4
        for (int o = 0; o < 128; o += 4) {
            float4 v = make_float4(sC[b * 129 + o] + bout[o] - lse,
                                   sC[b * 129 + o + 1] + bout[o + 1] - lse,
                                   sC[b * 129 + o + 2] + bout[o + 2] - lse,
                                   sC[b * 129 + o + 3] + bout[o + 3] - lse);
            *reinterpret_cast<float4*>(dst + o) = v;
        }
    }
}

// ---------------- host ----------------
extern "C" void kernel_launch(void* const* d_in, const int* in_sizes, int n_in,
                              void* d_out, int out_size) {
    const float* seq  = (const float*)d_in[0];
    const float* wih  = (const float*)d_in[1];
    const float* whh  = (const float*)d_in[2];
    const float* bih  = (const float*)d_in[3];
    const float* bhh  = (const float*)d_in[4];
    const float* wout = (const float*)d_in[5];
    const float* bout = (const float*)d_in[6];
    float* out = (float*)d_out;

    static bool attr_done = false;
    if (!attr_done) {
        cudaFuncSetAttribute(k_gi,   cudaFuncAttributeMaxDynamicSharedMemorySize, GI_SMEM);
        cudaFuncSetAttribute(k_step, cudaFuncAttributeMaxDynamicSharedMemorySize, SMEM_STEP);
        cudaFuncSetAttribute(k_out,  cudaFuncAttributeMaxDynamicSharedMemorySize, SMEM_OUT);
        attr_done = true;
    }

    {
        size_t n2 = (size_t)B_ * T_ * I_ / 2;
        k_conv_seq<<<(unsigned)((n2 + 255) / 256), 256>>>(seq);
    }
    {
        int total = G3H * I_ + G3H * H_ + O_ * H_ + BH_ / 2;
        k_conv_w<<<(total + 255) / 256, 256>>>(wih, whh, wout);
    }
    {
        dim3 grid(1024, 24);
        k_gi<<<grid, 256, GI_SMEM>>>(0);
    }
    k_step<<<NCTA, 256, SMEM_STEP>>>(bih, bhh);
    k_out<<<TS_, 256, SMEM_OUT>>>(bout, out);
}